// round 14
// baseline (speedup 1.0000x reference)
#include <cuda_runtime.h>
#include <cuda_bf16.h>
#include <cstring>
#include <cstdint>

// Shapes
#define BB 32
#define TT 64
#define NN 300
#define DD 128
#define ND (NN*DD)          // 38400
#define BT (BB*TT)          // 2048

#define SA_STRIDE 36        // A row stride (uint32), padded, conflict-free
#define A_WORDS (TT*SA_STRIDE)   // 2304 u32 = 9216 B per batch per array
#define A_BYTES 9216

// Scratch (static __device__ — no allocation allowed)
__device__ float    g_Q[BB*TT*NN];      // [b,t,n]
__device__ float    g_K[BB*TT*DD];      // [b,t,d]
__device__ float    g_S[BB*TT*TT];      // scores [b,q,k]
__device__ uint32_t g_Ah[BB*A_WORDS];   // att^T bf16x2 hi, PRE-PADDED stride 36
__device__ uint32_t g_Al[BB*A_WORDS];   // att^T bf16x2 lo, PRE-PADDED stride 36

__device__ __forceinline__ float bf16_round(float v) {
    return __bfloat162float(__float2bfloat16_rn(v));
}
// pack two floats as bf16x2; 'lo' goes to bits [15:0] (lower k index)
__device__ __forceinline__ uint32_t pack_bf16x2(float lo, float hi) {
    uint32_t r;
    asm("cvt.rn.bf16x2.f32 %0, %1, %2;" : "=r"(r) : "f"(hi), "f"(lo));
    return r;
}

// ---- bulk-copy / mbarrier primitives ----
__device__ __forceinline__ void bulk_ld(uint32_t dst_smem, const void* src,
                                        uint32_t bytes, uint32_t mbar) {
    asm volatile(
        "cp.async.bulk.shared::cluster.global.mbarrier::complete_tx::bytes "
        "[%0], [%1], %2, [%3];"
        :: "r"(dst_smem), "l"(src), "r"(bytes), "r"(mbar) : "memory");
}
__device__ __forceinline__ void bulk_st(void* dst, uint32_t src_smem, uint32_t bytes) {
    asm volatile(
        "cp.async.bulk.global.shared::cta.bulk_group [%0], [%1], %2;"
        :: "l"(dst), "r"(src_smem), "r"(bytes) : "memory");
}
__device__ __forceinline__ void mbar_init(uint32_t mbar, uint32_t count) {
    asm volatile("mbarrier.init.shared.b64 [%0], %1;" :: "r"(mbar), "r"(count) : "memory");
}
__device__ __forceinline__ void mbar_expect_tx(uint32_t mbar, uint32_t bytes) {
    asm volatile("mbarrier.arrive.expect_tx.shared.b64 _, [%0], %1;"
                 :: "r"(mbar), "r"(bytes) : "memory");
}
__device__ __forceinline__ void mbar_wait(uint32_t mbar, uint32_t parity) {
    uint32_t done = 0;
    while (!done) {
        asm volatile(
            "{\n\t.reg .pred p;\n\t"
            "mbarrier.try_wait.parity.shared::cta.b64 p, [%1], %2;\n\t"
            "selp.b32 %0, 1, 0, p;\n\t}"
            : "=r"(done) : "r"(mbar), "r"(parity) : "memory");
    }
}

// ---------------------------------------------------------------------------
// Kernel 1 (FUSED, single pass over src):
//   Q[bt,n] = dot(src[bt,n,:], wt1);  K[bt,d] = sum_n wt3[n]*src[bt,n,d]
// ---------------------------------------------------------------------------
#define SP_STRIDE 33

__global__ void __launch_bounds__(256)
qk_kernel(const float* __restrict__ src,
          const float* __restrict__ wt1,
          const float* __restrict__ wt3) {
    const int bt  = blockIdx.x;
    const int tid = threadIdx.x;
    const float* base = src + (size_t)bt * ND;

    __shared__ float  sw3[NN];
    __shared__ float  sP[NN * SP_STRIDE];
    __shared__ float4 sKred[8][32];

    for (int i = tid; i < NN; i += 256) sw3[i] = wt3[i];
    __syncthreads();

    const int warp = tid >> 5, lane = tid & 31;
    const float4 w1v = reinterpret_cast<const float4*>(wt1)[lane];
    float4 kacc = make_float4(0.f, 0.f, 0.f, 0.f);

    #pragma unroll 8
    for (int n = warp; n < NN; n += 8) {
        const float4 v = reinterpret_cast<const float4*>(base + n * DD)[lane];
        const float w3n = sw3[n];
        kacc.x += w3n * v.x; kacc.y += w3n * v.y;
        kacc.z += w3n * v.z; kacc.w += w3n * v.w;
        sP[n * SP_STRIDE + lane] =
            v.x * w1v.x + v.y * w1v.y + v.z * w1v.z + v.w * w1v.w;
    }

    sKred[warp][lane] = kacc;
    __syncthreads();

    for (int n = tid; n < NN; n += 256) {
        const float* row = sP + n * SP_STRIDE;
        float s = 0.f;
        #pragma unroll
        for (int j = 0; j < 32; ++j) s += row[j];
        g_Q[bt * NN + n] = s;
    }

    if (tid < 128) {
        const int l = tid >> 2, comp = tid & 3;
        float s = 0.f;
        #pragma unroll
        for (int w = 0; w < 8; ++w)
            s += reinterpret_cast<const float*>(&sKred[w][l])[comp];
        g_K[bt * DD + tid] = s;
    }
}

// ---------------------------------------------------------------------------
// Kernel 2 (FUSED m+scores): per (b, 8-q tile) — 256 CTAs, warp = 1 q row.
// ---------------------------------------------------------------------------
__global__ void __launch_bounds__(256)
mscores_kernel(const float* __restrict__ wt2) {
    const int b = blockIdx.x, qt = blockIdx.y;
    const int tid = threadIdx.x;
    const int warp = tid >> 5, lane = tid & 31;

    __shared__ float sQ[8 * NN];
    __shared__ float sM[8 * DD];
    __shared__ float sK[TT * 129];

    for (int i = tid; i < 8 * NN; i += 256)
        sQ[i] = g_Q[(b * TT + qt * 8) * NN + i];
    for (int i = tid; i < TT * DD; i += 256) {
        const int k = i >> 7, d = i & 127;
        sK[k * 129 + d] = g_K[(b * TT + k) * DD + d];
    }
    __syncthreads();

    {
        const int q = warp;
        float acc[4] = {0.f, 0.f, 0.f, 0.f};
        #pragma unroll 4
        for (int n = 0; n < NN; ++n) {
            const float qv = sQ[q * NN + n];
            const float* w2 = wt2 + n * DD;
            #pragma unroll
            for (int j = 0; j < 4; ++j)
                acc[j] += qv * w2[lane + 32 * j];
        }
        #pragma unroll
        for (int j = 0; j < 4; ++j)
            sM[q * DD + lane + 32 * j] = acc[j];
    }
    __syncthreads();

    #pragma unroll
    for (int pi = 0; pi < 2; ++pi) {
        const int p = pi * 256 + tid;
        const int q = p >> 6, k = p & 63;
        float acc = 0.f;
        #pragma unroll 8
        for (int d = 0; d < DD; ++d)
            acc += sM[q * DD + d] * sK[k * 129 + d];
        g_S[(b * TT + qt * 8 + q) * TT + k] = acc;
    }
}

// ---------------------------------------------------------------------------
// Kernel 3: softmax over BATCH axis + transpose + bf16 hi/lo pre-pack,
// written PRE-PADDED (stride 36) so mix can bulk-copy A contiguously.
// ---------------------------------------------------------------------------
__global__ void __launch_bounds__(256)
softmax_kernel() {
    const int warp = threadIdx.x >> 5, lane = threadIdx.x & 31;
    const int w  = blockIdx.x * 8 + warp;
    const int a  = w >> 5, tp = w & 31;

    const float x0 = g_S[lane * (TT * TT) + (2 * tp) * TT + a];
    const float x1 = g_S[lane * (TT * TT) + (2 * tp + 1) * TT + a];
    float m0 = x0, m1 = x1;
    #pragma unroll
    for (int off = 16; off > 0; off >>= 1) {
        m0 = fmaxf(m0, __shfl_xor_sync(0xffffffffu, m0, off));
        m1 = fmaxf(m1, __shfl_xor_sync(0xffffffffu, m1, off));
    }
    const float e0 = __expf(x0 - m0), e1 = __expf(x1 - m1);
    float s0 = e0, s1 = e1;
    #pragma unroll
    for (int off = 16; off > 0; off >>= 1) {
        s0 += __shfl_xor_sync(0xffffffffu, s0, off);
        s1 += __shfl_xor_sync(0xffffffffu, s1, off);
    }
    const float v0 = e0 / s0, v1 = e1 / s1;
    const float h0 = bf16_round(v0), h1 = bf16_round(v1);
    const int idx = a * SA_STRIDE + tp;
    g_Ah[lane * A_WORDS + idx] = pack_bf16x2(h0, h1);
    g_Al[lane * A_WORDS + idx] = pack_bf16x2(v0 - h0, v1 - h1);
}

// ---------------------------------------------------------------------------
// Kernel 4 (TENSOR): DOUBLE-BUFFERED TILE PIPELINE on the bulk engine.
// Each CTA: strip of 4 x 128-col tiles; A loaded once; load(i+1) overlaps
// compute(i) overlaps store(i-1). 2 CTAs/SM.
// ---------------------------------------------------------------------------
#define NT 4                 // tiles per CTA
#define SS_STRIDE 132        // floats; 528B row pitch (16B-aligned); conflict-free
#define BUF_FLOATS (TT*SS_STRIDE)       // 8448
#define TILE_BYTES (TT*SS_STRIDE*4)     // 33792 (row payload 512B each)
// floats: 2*8448 + (2304+2304 u32) = 21504; + 16B mbars
#define MIX_SMEM_BYTES (21504*4 + 16)   // 86032

__device__ __forceinline__ void mma_bf16(float c[4],
                                         uint32_t a0, uint32_t a1,
                                         uint32_t a2, uint32_t a3,
                                         uint32_t b0, uint32_t b1) {
    asm volatile(
        "mma.sync.aligned.m16n8k16.row.col.f32.bf16.bf16.f32 "
        "{%0,%1,%2,%3}, {%4,%5,%6,%7}, {%8,%9}, {%0,%1,%2,%3};"
        : "+f"(c[0]), "+f"(c[1]), "+f"(c[2]), "+f"(c[3])
        : "r"(a0), "r"(a1), "r"(a2), "r"(a3), "r"(b0), "r"(b1));
}

__global__ void __launch_bounds__(256, 2)
mix_kernel(const float* __restrict__ src, float* __restrict__ out) {
    extern __shared__ float smem[];
    float*    sS0 = smem;                       // buf 0
    float*    sS1 = smem + BUF_FLOATS;          // buf 1
    uint32_t* sAh = (uint32_t*)(smem + 2 * BUF_FLOATS);
    uint32_t* sAl = sAh + A_WORDS;
    uint64_t* mb  = (uint64_t*)(sAl + A_WORDS); // 2 mbarriers

    const int b     = blockIdx.y;
    const int strip = blockIdx.x;               // 0..74
    const int tid   = threadIdx.x;
    const int warp  = tid >> 5, lane = tid & 31;

    float* sSbuf[2] = {sS0, sS1};
    uint32_t sS_a[2];
    sS_a[0] = (uint32_t)__cvta_generic_to_shared(sS0);
    sS_a[1] = (uint32_t)__cvta_generic_to_shared(sS1);
    const uint32_t sAh_a = (uint32_t)__cvta_generic_to_shared(sAh);
    const uint32_t sAl_a = (uint32_t)__cvta_generic_to_shared(sAl);
    uint32_t mb_a[2];
    mb_a[0] = (uint32_t)__cvta_generic_to_shared(mb);
    mb_a[1] = mb_a[0] + 8;

    const float* sbase = src + (size_t)b * TT * ND + strip * (NT * DD);
    float*       obase = out + (size_t)b * TT * ND + strip * (NT * DD);

    // --- init + first loads (tile 0 + A) ---
    if (tid == 0) { mbar_init(mb_a[0], 1); mbar_init(mb_a[1], 1); }
    __syncthreads();
    if (tid == 0) mbar_expect_tx(mb_a[0], TILE_BYTES / 528 * 512 + 2 * A_BYTES
                                          + (TILE_BYTES - TT * 528));  // = 64*512 + 2*9216
    __syncthreads();
    if (tid < TT) {
        bulk_ld(sS_a[0] + tid * 528, sbase + (size_t)tid * ND, 512, mb_a[0]);
    } else if (tid == 64) {
        bulk_ld(sAh_a, g_Ah + b * A_WORDS, A_BYTES, mb_a[0]);
    } else if (tid == 65) {
        bulk_ld(sAl_a, g_Al + b * A_WORDS, A_BYTES, mb_a[0]);
    }

    const int g   = lane >> 2;
    const int tg  = lane & 3;
    const int mg  = warp >> 2;          // m-group: rows mg*32..mg*32+31
    const int n0w = (warp & 3) * 32;    // col-group

    for (int i = 0; i < NT; ++i) {
        const int buf = i & 1;
        mbar_wait(mb_a[buf], (i >> 1) & 1);

        // --- prefetch tile i+1 into the other buffer ---
        if (i + 1 < NT) {
            if (i >= 1) {
                // other buffer held tile i-1: its store must have read smem
                asm volatile("cp.async.bulk.wait_group.read 0;" ::: "memory");
            }
            __syncthreads();
            if (tid == 0) mbar_expect_tx(mb_a[(i + 1) & 1], TT * 512);
            __syncthreads();
            if (tid < TT)
                bulk_ld(sS_a[(i + 1) & 1] + tid * 528,
                        sbase + (size_t)(i + 1) * DD + (size_t)tid * ND,
                        512, mb_a[(i + 1) & 1]);
        }

        float* sS = sSbuf[buf];

        float acc[2][4][4];
        #pragma unroll
        for (int mi = 0; mi < 2; ++mi)
            #pragma unroll
            for (int nt = 0; nt < 4; ++nt)
                #pragma unroll
                for (int f = 0; f < 4; ++f) acc[mi][nt][f] = 0.f;

        #pragma unroll
        for (int ks = 0; ks < 4; ++ks) {
            uint32_t Bh0[4], Bh1[4], Bl0[4], Bl1[4];
            #pragma unroll
            for (int nt = 0; nt < 4; ++nt) {
                const int c  = n0w + nt * 8 + g;
                const int t0 = ks * 16 + 2 * tg;
                const float v0 = sS[(t0)     * SS_STRIDE + c];
                const float v1 = sS[(t0 + 1) * SS_STRIDE + c];
                const float v2 = sS[(t0 + 8) * SS_STRIDE + c];
                const float v3 = sS[(t0 + 9) * SS_STRIDE + c];
                const float h0 = bf16_round(v0), h1 = bf16_round(v1);
                const float h2 = bf16_round(v2), h3 = bf16_round(v3);
                Bh0[nt] = pack_bf16x2(h0, h1);
                Bh1[nt] = pack_bf16x2(h2, h3);
                Bl0[nt] = pack_bf16x2(v0 - h0, v1 - h1);
                Bl1[nt] = pack_bf16x2(v2 - h2, v3 - h3);
            }
            #pragma unroll
            for (int mi = 0; mi < 2; ++mi) {
                const int mt = mg * 2 + mi;
                const int r0 = (mt * 16 + g) * SA_STRIDE + ks * 8 + tg;
                const int r1 = r0 + 8 * SA_STRIDE;
                const uint32_t ah0 = sAh[r0],     ah1 = sAh[r1];
                const uint32_t ah2 = sAh[r0 + 4], ah3 = sAh[r1 + 4];
                const uint32_t al0 = sAl[r0],     al1 = sAl[r1];
                const uint32_t al2 = sAl[r0 + 4], al3 = sAl[r1 + 4];
                #pragma unroll
                for (int nt = 0; nt < 4; ++nt) {
                    mma_bf16(acc[mi][nt], ah0, ah1, ah2, ah3, Bh0[nt], Bh1[nt]);
                    mma_bf16(acc[mi][nt], al0, al1, al2, al3, Bh0[nt], Bh1[nt]);
                    mma_bf16(acc[mi][nt], ah0, ah1, ah2, ah3, Bl0[nt], Bl1[nt]);
                }
            }
        }

        // --- epilogue: residual add (read before overwrite), stage, bulk store ---
        #pragma unroll
        for (int mi = 0; mi < 2; ++mi) {
            const int a0 = (mg * 2 + mi) * 16 + g;
            #pragma unroll
            for (int nt = 0; nt < 4; ++nt) {
                const int c = n0w + nt * 8 + 2 * tg;
                const float2 r0 = *reinterpret_cast<const float2*>(sS + a0 * SS_STRIDE + c);
                const float2 r1 = *reinterpret_cast<const float2*>(sS + (a0 + 8) * SS_STRIDE + c);
                acc[mi][nt][0] += r0.x; acc[mi][nt][1] += r0.y;
                acc[mi][nt][2] += r1.x; acc[mi][nt][3] += r1.y;
            }
        }
        __syncthreads();
        #pragma unroll
        for (int mi = 0; mi < 2; ++mi) {
            const int a0 = (mg * 2 + mi) * 16 + g;
            #pragma unroll
            for (int nt = 0; nt < 4; ++nt) {
                const int c = n0w + nt * 8 + 2 * tg;
                *reinterpret_cast<float2*>(sS + a0 * SS_STRIDE + c) =
                    make_float2(acc[mi][nt][0], acc[mi][nt][1]);
                *reinterpret_cast<float2*>(sS + (a0 + 8) * SS_STRIDE + c) =
                    make_float2(acc[mi][nt][2], acc[mi][nt][3]);
            }
        }
        __syncthreads();

        if (tid < TT) {
            asm volatile("fence.proxy.async;" ::: "memory");
            bulk_st(obase + (size_t)i * DD + (size_t)tid * ND,
                    sS_a[buf] + tid * 528, 512);
            asm volatile("cp.async.bulk.commit_group;" ::: "memory");
        }
    }

    asm volatile("cp.async.bulk.wait_group 0;" ::: "memory");
}

// ---------------------------------------------------------------------------
extern "C" void kernel_launch(void* const* d_in, const int* in_sizes, int n_in,
                              void* d_out, int out_size) {
    const float *src = nullptr, *wt1 = nullptr, *wt2 = nullptr, *wt3 = nullptr;
    for (int i = 0; i < n_in; ++i) {
        const int s = in_sizes[i];
        if      (s == BB * TT * NN * DD) src = (const float*)d_in[i];
        else if (s == DD)                wt1 = (const float*)d_in[i];
        else if (s == NN * DD)           wt2 = (const float*)d_in[i];
        else if (s == NN)                wt3 = (const float*)d_in[i];
    }
    float* out = (float*)d_out;

    static bool attr_done = false;
    if (!attr_done) {
        cudaFuncSetAttribute(mix_kernel,
                             cudaFuncAttributeMaxDynamicSharedMemorySize,
                             MIX_SMEM_BYTES);
        attr_done = true;
    }

    qk_kernel<<<BT, 256>>>(src, wt1, wt3);
    mscores_kernel<<<dim3(BB, 8), 256>>>(wt2);
    softmax_kernel<<<256, 256>>>();
    mix_kernel<<<dim3(ND / (NT * DD), BB), 256, MIX_SMEM_BYTES>>>(src, out);
}

// round 15
// speedup vs baseline: 1.0805x; 1.0805x over previous
#include <cuda_runtime.h>
#include <cuda_bf16.h>
#include <cstring>
#include <cstdint>

// Shapes
#define BB 32
#define TT 64
#define NN 300
#define DD 128
#define ND (NN*DD)          // 38400
#define BT (BB*TT)          // 2048

#define SA_STRIDE 36        // A row stride (uint32), padded, conflict-free
#define A_WORDS (TT*SA_STRIDE)   // 2304 u32 = 9216 B per batch per array
#define A_BYTES 9216

// Scratch (static __device__ — no allocation allowed)
__device__ float    g_Q[BB*TT*NN];      // [b,t,n]
__device__ float    g_K[BB*TT*DD];      // [b,t,d]
__device__ float    g_S[BB*TT*TT];      // scores [b,q,k]
__device__ uint32_t g_Ah[BB*A_WORDS];   // att^T bf16x2 hi, PRE-PADDED stride 36
__device__ uint32_t g_Al[BB*A_WORDS];   // att^T bf16x2 lo, PRE-PADDED stride 36

__device__ __forceinline__ float bf16_round(float v) {
    return __bfloat162float(__float2bfloat16_rn(v));
}
// pack two floats as bf16x2; 'lo' goes to bits [15:0] (lower k index)
__device__ __forceinline__ uint32_t pack_bf16x2(float lo, float hi) {
    uint32_t r;
    asm("cvt.rn.bf16x2.f32 %0, %1, %2;" : "=r"(r) : "f"(hi), "f"(lo));
    return r;
}

// ---- bulk-copy / mbarrier primitives ----
__device__ __forceinline__ void bulk_ld(uint32_t dst_smem, const void* src,
                                        uint32_t bytes, uint32_t mbar) {
    asm volatile(
        "cp.async.bulk.shared::cluster.global.mbarrier::complete_tx::bytes "
        "[%0], [%1], %2, [%3];"
        :: "r"(dst_smem), "l"(src), "r"(bytes), "r"(mbar) : "memory");
}
__device__ __forceinline__ void bulk_st(void* dst, uint32_t src_smem, uint32_t bytes) {
    asm volatile(
        "cp.async.bulk.global.shared::cta.bulk_group [%0], [%1], %2;"
        :: "l"(dst), "r"(src_smem), "r"(bytes) : "memory");
}
__device__ __forceinline__ void mbar_init(uint32_t mbar, uint32_t count) {
    asm volatile("mbarrier.init.shared.b64 [%0], %1;" :: "r"(mbar), "r"(count) : "memory");
}
__device__ __forceinline__ void mbar_expect_tx(uint32_t mbar, uint32_t bytes) {
    asm volatile("mbarrier.arrive.expect_tx.shared.b64 _, [%0], %1;"
                 :: "r"(mbar), "r"(bytes) : "memory");
}
__device__ __forceinline__ void mbar_wait(uint32_t mbar, uint32_t parity) {
    uint32_t done = 0;
    while (!done) {
        asm volatile(
            "{\n\t.reg .pred p;\n\t"
            "mbarrier.try_wait.parity.shared::cta.b64 p, [%1], %2;\n\t"
            "selp.b32 %0, 1, 0, p;\n\t}"
            : "=r"(done) : "r"(mbar), "r"(parity) : "memory");
    }
}

// ---------------------------------------------------------------------------
// Kernel 1 (FUSED, single pass over src):
//   Q[bt,n] = dot(src[bt,n,:], wt1);  K[bt,d] = sum_n wt3[n]*src[bt,n,d]
// ---------------------------------------------------------------------------
#define SP_STRIDE 33

__global__ void __launch_bounds__(256)
qk_kernel(const float* __restrict__ src,
          const float* __restrict__ wt1,
          const float* __restrict__ wt3) {
    const int bt  = blockIdx.x;
    const int tid = threadIdx.x;
    const float* base = src + (size_t)bt * ND;

    __shared__ float  sw3[NN];
    __shared__ float  sP[NN * SP_STRIDE];
    __shared__ float4 sKred[8][32];

    for (int i = tid; i < NN; i += 256) sw3[i] = wt3[i];
    __syncthreads();

    const int warp = tid >> 5, lane = tid & 31;
    const float4 w1v = reinterpret_cast<const float4*>(wt1)[lane];
    float4 kacc = make_float4(0.f, 0.f, 0.f, 0.f);

    #pragma unroll 8
    for (int n = warp; n < NN; n += 8) {
        const float4 v = reinterpret_cast<const float4*>(base + n * DD)[lane];
        const float w3n = sw3[n];
        kacc.x += w3n * v.x; kacc.y += w3n * v.y;
        kacc.z += w3n * v.z; kacc.w += w3n * v.w;
        sP[n * SP_STRIDE + lane] =
            v.x * w1v.x + v.y * w1v.y + v.z * w1v.z + v.w * w1v.w;
    }

    sKred[warp][lane] = kacc;
    __syncthreads();

    for (int n = tid; n < NN; n += 256) {
        const float* row = sP + n * SP_STRIDE;
        float s = 0.f;
        #pragma unroll
        for (int j = 0; j < 32; ++j) s += row[j];
        g_Q[bt * NN + n] = s;
    }

    if (tid < 128) {
        const int l = tid >> 2, comp = tid & 3;
        float s = 0.f;
        #pragma unroll
        for (int w = 0; w < 8; ++w)
            s += reinterpret_cast<const float*>(&sKred[w][l])[comp];
        g_K[bt * DD + tid] = s;
    }
}

// ---------------------------------------------------------------------------
// Kernel 2 (FUSED m+scores): per (b, 8-q tile) — 256 CTAs, warp = 1 q row.
// ---------------------------------------------------------------------------
__global__ void __launch_bounds__(256)
mscores_kernel(const float* __restrict__ wt2) {
    const int b = blockIdx.x, qt = blockIdx.y;
    const int tid = threadIdx.x;
    const int warp = tid >> 5, lane = tid & 31;

    __shared__ float sQ[8 * NN];
    __shared__ float sM[8 * DD];
    __shared__ float sK[TT * 129];

    for (int i = tid; i < 8 * NN; i += 256)
        sQ[i] = g_Q[(b * TT + qt * 8) * NN + i];
    for (int i = tid; i < TT * DD; i += 256) {
        const int k = i >> 7, d = i & 127;
        sK[k * 129 + d] = g_K[(b * TT + k) * DD + d];
    }
    __syncthreads();

    {
        const int q = warp;
        float acc[4] = {0.f, 0.f, 0.f, 0.f};
        #pragma unroll 4
        for (int n = 0; n < NN; ++n) {
            const float qv = sQ[q * NN + n];
            const float* w2 = wt2 + n * DD;
            #pragma unroll
            for (int j = 0; j < 4; ++j)
                acc[j] += qv * w2[lane + 32 * j];
        }
        #pragma unroll
        for (int j = 0; j < 4; ++j)
            sM[q * DD + lane + 32 * j] = acc[j];
    }
    __syncthreads();

    #pragma unroll
    for (int pi = 0; pi < 2; ++pi) {
        const int p = pi * 256 + tid;
        const int q = p >> 6, k = p & 63;
        float acc = 0.f;
        #pragma unroll 8
        for (int d = 0; d < DD; ++d)
            acc += sM[q * DD + d] * sK[k * 129 + d];
        g_S[(b * TT + qt * 8 + q) * TT + k] = acc;
    }
}

// ---------------------------------------------------------------------------
// Kernel 3: softmax over BATCH axis + transpose + bf16 hi/lo pre-pack,
// written PRE-PADDED (stride 36) so mix can bulk-copy A contiguously.
// ---------------------------------------------------------------------------
__global__ void __launch_bounds__(256)
softmax_kernel() {
    const int warp = threadIdx.x >> 5, lane = threadIdx.x & 31;
    const int w  = blockIdx.x * 8 + warp;
    const int a  = w >> 5, tp = w & 31;

    const float x0 = g_S[lane * (TT * TT) + (2 * tp) * TT + a];
    const float x1 = g_S[lane * (TT * TT) + (2 * tp + 1) * TT + a];
    float m0 = x0, m1 = x1;
    #pragma unroll
    for (int off = 16; off > 0; off >>= 1) {
        m0 = fmaxf(m0, __shfl_xor_sync(0xffffffffu, m0, off));
        m1 = fmaxf(m1, __shfl_xor_sync(0xffffffffu, m1, off));
    }
    const float e0 = __expf(x0 - m0), e1 = __expf(x1 - m1);
    float s0 = e0, s1 = e1;
    #pragma unroll
    for (int off = 16; off > 0; off >>= 1) {
        s0 += __shfl_xor_sync(0xffffffffu, s0, off);
        s1 += __shfl_xor_sync(0xffffffffu, s1, off);
    }
    const float v0 = e0 / s0, v1 = e1 / s1;
    const float h0 = bf16_round(v0), h1 = bf16_round(v1);
    const int idx = a * SA_STRIDE + tp;
    g_Ah[lane * A_WORDS + idx] = pack_bf16x2(h0, h1);
    g_Al[lane * A_WORDS + idx] = pack_bf16x2(v0 - h0, v1 - h1);
}

// ---------------------------------------------------------------------------
// Kernel 4 (TENSOR): bulk-engine I/O (round-13) + 3 CTAs/SM (round-9 tiling).
// mixed[a,c] = sum_t att^T[a,t]*src[t,c]; out = mixed + src.
// 64x128 tile; warp = 2 m-groups x 4 col-groups; acc 32 regs.
// ---------------------------------------------------------------------------
#define SS_STRIDE 132   // floats; 528B row pitch (16B-aligned); conflict-free
// bytes: sS 33792 + sAh 9216 + sAl 9216 + mbar 16 = 52240
#define MIX_SMEM_BYTES 52240
#define TOTAL_TX (TT*512 + 2*A_BYTES)   // 32768 + 18432 = 51200

__device__ __forceinline__ void mma_bf16(float c[4],
                                         uint32_t a0, uint32_t a1,
                                         uint32_t a2, uint32_t a3,
                                         uint32_t b0, uint32_t b1) {
    asm volatile(
        "mma.sync.aligned.m16n8k16.row.col.f32.bf16.bf16.f32 "
        "{%0,%1,%2,%3}, {%4,%5,%6,%7}, {%8,%9}, {%0,%1,%2,%3};"
        : "+f"(c[0]), "+f"(c[1]), "+f"(c[2]), "+f"(c[3])
        : "r"(a0), "r"(a1), "r"(a2), "r"(a3), "r"(b0), "r"(b1));
}

__global__ void __launch_bounds__(256, 3)
mix_kernel(const float* __restrict__ src, float* __restrict__ out) {
    extern __shared__ float smem[];
    float*    sS  = smem;                               // [64][132]
    uint32_t* sAh = (uint32_t*)(smem + TT * SS_STRIDE); // [64][36] padded
    uint32_t* sAl = sAh + A_WORDS;
    uint64_t* mb  = (uint64_t*)(sAl + A_WORDS);

    const int b    = blockIdx.y;
    const int tid  = threadIdx.x;
    const int warp = tid >> 5, lane = tid & 31;
    const int colbase = blockIdx.x * 128;

    const uint32_t sS_a  = (uint32_t)__cvta_generic_to_shared(sS);
    const uint32_t sAh_a = (uint32_t)__cvta_generic_to_shared(sAh);
    const uint32_t sAl_a = (uint32_t)__cvta_generic_to_shared(sAl);
    const uint32_t mb_a  = (uint32_t)__cvta_generic_to_shared(mb);

    const float* sb = src + (size_t)b * TT * ND + colbase;

    // --- mbarrier setup + bulk loads (64 rows x 512B + 2 A arrays) ---
    if (tid == 0) mbar_init(mb_a, 1);
    __syncthreads();
    if (tid == 0) mbar_expect_tx(mb_a, TOTAL_TX);
    __syncthreads();
    if (tid < TT) {
        bulk_ld(sS_a + tid * (SS_STRIDE * 4), sb + (size_t)tid * ND, 512, mb_a);
    } else if (tid == 64) {
        bulk_ld(sAh_a, g_Ah + b * A_WORDS, A_BYTES, mb_a);
    } else if (tid == 65) {
        bulk_ld(sAl_a, g_Al + b * A_WORDS, A_BYTES, mb_a);
    }
    mbar_wait(mb_a, 0);

    const int g   = lane >> 2;
    const int tg  = lane & 3;
    const int mg  = warp >> 2;          // m-group: rows mg*32..mg*32+31
    const int n0w = (warp & 3) * 32;    // col-group

    float acc[2][4][4];
    #pragma unroll
    for (int mi = 0; mi < 2; ++mi)
        #pragma unroll
        for (int nt = 0; nt < 4; ++nt)
            #pragma unroll
            for (int f = 0; f < 4; ++f) acc[mi][nt][f] = 0.f;

    #pragma unroll
    for (int ks = 0; ks < 4; ++ks) {
        // --- stage B fragments for all 4 nt (16 regs) ---
        uint32_t Bh0[4], Bh1[4], Bl0[4], Bl1[4];
        #pragma unroll
        for (int nt = 0; nt < 4; ++nt) {
            const int c  = n0w + nt * 8 + g;
            const int t0 = ks * 16 + 2 * tg;
            const float v0 = sS[(t0)     * SS_STRIDE + c];
            const float v1 = sS[(t0 + 1) * SS_STRIDE + c];
            const float v2 = sS[(t0 + 8) * SS_STRIDE + c];
            const float v3 = sS[(t0 + 9) * SS_STRIDE + c];
            const float h0 = bf16_round(v0), h1 = bf16_round(v1);
            const float h2 = bf16_round(v2), h3 = bf16_round(v3);
            Bh0[nt] = pack_bf16x2(h0, h1);
            Bh1[nt] = pack_bf16x2(h2, h3);
            Bl0[nt] = pack_bf16x2(v0 - h0, v1 - h1);
            Bl1[nt] = pack_bf16x2(v2 - h2, v3 - h3);
        }
        // --- per m-tile (2): load A just-in-time, fire 12 MMAs ---
        #pragma unroll
        for (int mi = 0; mi < 2; ++mi) {
            const int mt = mg * 2 + mi;
            const int r0 = (mt * 16 + g) * SA_STRIDE + ks * 8 + tg;
            const int r1 = r0 + 8 * SA_STRIDE;
            const uint32_t ah0 = sAh[r0],     ah1 = sAh[r1];
            const uint32_t ah2 = sAh[r0 + 4], ah3 = sAh[r1 + 4];
            const uint32_t al0 = sAl[r0],     al1 = sAl[r1];
            const uint32_t al2 = sAl[r0 + 4], al3 = sAl[r1 + 4];
            #pragma unroll
            for (int nt = 0; nt < 4; ++nt) {
                mma_bf16(acc[mi][nt], ah0, ah1, ah2, ah3, Bh0[nt], Bh1[nt]);
                mma_bf16(acc[mi][nt], al0, al1, al2, al3, Bh0[nt], Bh1[nt]);
                mma_bf16(acc[mi][nt], ah0, ah1, ah2, ah3, Bl0[nt], Bl1[nt]);
            }
        }
    }

    // --- epilogue: residual add (read before overwrite), stage, bulk store ---
    #pragma unroll
    for (int mi = 0; mi < 2; ++mi) {
        const int a0 = (mg * 2 + mi) * 16 + g;
        #pragma unroll
        for (int nt = 0; nt < 4; ++nt) {
            const int c = n0w + nt * 8 + 2 * tg;
            const float2 r0 = *reinterpret_cast<const float2*>(sS + a0 * SS_STRIDE + c);
            const float2 r1 = *reinterpret_cast<const float2*>(sS + (a0 + 8) * SS_STRIDE + c);
            acc[mi][nt][0] += r0.x; acc[mi][nt][1] += r0.y;
            acc[mi][nt][2] += r1.x; acc[mi][nt][3] += r1.y;
        }
    }
    __syncthreads();
    #pragma unroll
    for (int mi = 0; mi < 2; ++mi) {
        const int a0 = (mg * 2 + mi) * 16 + g;
        #pragma unroll
        for (int nt = 0; nt < 4; ++nt) {
            const int c = n0w + nt * 8 + 2 * tg;
            *reinterpret_cast<float2*>(sS + a0 * SS_STRIDE + c) =
                make_float2(acc[mi][nt][0], acc[mi][nt][1]);
            *reinterpret_cast<float2*>(sS + (a0 + 8) * SS_STRIDE + c) =
                make_float2(acc[mi][nt][2], acc[mi][nt][3]);
        }
    }
    __syncthreads();

    float* ob = out + (size_t)b * TT * ND + colbase;
    if (tid < TT) {
        asm volatile("fence.proxy.async;" ::: "memory");
        bulk_st(ob + (size_t)tid * ND, sS_a + tid * (SS_STRIDE * 4), 512);
        asm volatile("cp.async.bulk.commit_group;" ::: "memory");
        asm volatile("cp.async.bulk.wait_group.read 0;" ::: "memory");
    }
}

// ---------------------------------------------------------------------------
extern "C" void kernel_launch(void* const* d_in, const int* in_sizes, int n_in,
                              void* d_out, int out_size) {
    const float *src = nullptr, *wt1 = nullptr, *wt2 = nullptr, *wt3 = nullptr;
    for (int i = 0; i < n_in; ++i) {
        const int s = in_sizes[i];
        if      (s == BB * TT * NN * DD) src = (const float*)d_in[i];
        else if (s == DD)                wt1 = (const float*)d_in[i];
        else if (s == NN * DD)           wt2 = (const float*)d_in[i];
        else if (s == NN)                wt3 = (const float*)d_in[i];
    }
    float* out = (float*)d_out;

    static bool attr_done = false;
    if (!attr_done) {
        cudaFuncSetAttribute(mix_kernel,
                             cudaFuncAttributeMaxDynamicSharedMemorySize,
                             MIX_SMEM_BYTES);
        attr_done = true;
    }

    qk_kernel<<<BT, 256>>>(src, wt1, wt3);
    mscores_kernel<<<dim3(BB, 8), 256>>>(wt2);
    softmax_kernel<<<256, 256>>>();
    mix_kernel<<<dim3(ND / 128, BB), 256, MIX_SMEM_BYTES>>>(src, out);
}

// round 16
// speedup vs baseline: 1.0851x; 1.0042x over previous
#include <cuda_runtime.h>
#include <cuda_bf16.h>
#include <cstring>
#include <cstdint>

// Shapes
#define BB 32
#define TT 64
#define NN 300
#define DD 128
#define ND (NN*DD)          // 38400
#define BT (BB*TT)          // 2048

#define SA_STRIDE 36        // A row stride (uint32), padded, conflict-free
#define A_WORDS (TT*SA_STRIDE)   // 2304 u32 = 9216 B per batch per array
#define A_BYTES 9216

// Scratch (static __device__ — no allocation allowed)
__device__ float    g_Q[BB*TT*NN];      // [b,t,n]
__device__ float    g_K[BB*TT*DD];      // [b,t,d]
__device__ float    g_S[BB*TT*TT];      // scores [b,q,k]
__device__ uint32_t g_Ah[BB*A_WORDS];   // att^T bf16x2 hi, PRE-PADDED stride 36
__device__ uint32_t g_Al[BB*A_WORDS];   // att^T bf16x2 lo, PRE-PADDED stride 36

__device__ __forceinline__ float bf16_round(float v) {
    return __bfloat162float(__float2bfloat16_rn(v));
}
// pack two floats as bf16x2; 'lo' goes to bits [15:0] (lower k index)
__device__ __forceinline__ uint32_t pack_bf16x2(float lo, float hi) {
    uint32_t r;
    asm("cvt.rn.bf16x2.f32 %0, %1, %2;" : "=r"(r) : "f"(hi), "f"(lo));
    return r;
}

// ---- bulk-copy / mbarrier primitives ----
__device__ __forceinline__ void bulk_ld(uint32_t dst_smem, const void* src,
                                        uint32_t bytes, uint32_t mbar) {
    asm volatile(
        "cp.async.bulk.shared::cluster.global.mbarrier::complete_tx::bytes "
        "[%0], [%1], %2, [%3];"
        :: "r"(dst_smem), "l"(src), "r"(bytes), "r"(mbar) : "memory");
}
__device__ __forceinline__ void bulk_st(void* dst, uint32_t src_smem, uint32_t bytes) {
    asm volatile(
        "cp.async.bulk.global.shared::cta.bulk_group [%0], [%1], %2;"
        :: "l"(dst), "r"(src_smem), "r"(bytes) : "memory");
}
__device__ __forceinline__ void mbar_init(uint32_t mbar, uint32_t count) {
    asm volatile("mbarrier.init.shared.b64 [%0], %1;" :: "r"(mbar), "r"(count) : "memory");
}
__device__ __forceinline__ void mbar_expect_tx(uint32_t mbar, uint32_t bytes) {
    asm volatile("mbarrier.arrive.expect_tx.shared.b64 _, [%0], %1;"
                 :: "r"(mbar), "r"(bytes) : "memory");
}
__device__ __forceinline__ void mbar_wait(uint32_t mbar, uint32_t parity) {
    uint32_t done = 0;
    while (!done) {
        asm volatile(
            "{\n\t.reg .pred p;\n\t"
            "mbarrier.try_wait.parity.shared::cta.b64 p, [%1], %2;\n\t"
            "selp.b32 %0, 1, 0, p;\n\t}"
            : "=r"(done) : "r"(mbar), "r"(parity) : "memory");
    }
}

// ---------------------------------------------------------------------------
// Kernel 1 (FUSED, single pass over src):
//   Q[bt,n] = dot(src[bt,n,:], wt1);  K[bt,d] = sum_n wt3[n]*src[bt,n,d]
// ---------------------------------------------------------------------------
#define SP_STRIDE 33

__global__ void __launch_bounds__(256)
qk_kernel(const float* __restrict__ src,
          const float* __restrict__ wt1,
          const float* __restrict__ wt3) {
    const int bt  = blockIdx.x;
    const int tid = threadIdx.x;
    const float* base = src + (size_t)bt * ND;

    __shared__ float  sw3[NN];
    __shared__ float  sP[NN * SP_STRIDE];
    __shared__ float4 sKred[8][32];

    for (int i = tid; i < NN; i += 256) sw3[i] = wt3[i];
    __syncthreads();

    const int warp = tid >> 5, lane = tid & 31;
    const float4 w1v = reinterpret_cast<const float4*>(wt1)[lane];
    float4 kacc = make_float4(0.f, 0.f, 0.f, 0.f);

    #pragma unroll 8
    for (int n = warp; n < NN; n += 8) {
        const float4 v = reinterpret_cast<const float4*>(base + n * DD)[lane];
        const float w3n = sw3[n];
        kacc.x += w3n * v.x; kacc.y += w3n * v.y;
        kacc.z += w3n * v.z; kacc.w += w3n * v.w;
        sP[n * SP_STRIDE + lane] =
            v.x * w1v.x + v.y * w1v.y + v.z * w1v.z + v.w * w1v.w;
    }

    sKred[warp][lane] = kacc;
    __syncthreads();

    for (int n = tid; n < NN; n += 256) {
        const float* row = sP + n * SP_STRIDE;
        float s = 0.f;
        #pragma unroll
        for (int j = 0; j < 32; ++j) s += row[j];
        g_Q[bt * NN + n] = s;
    }

    if (tid < 128) {
        const int l = tid >> 2, comp = tid & 3;
        float s = 0.f;
        #pragma unroll
        for (int w = 0; w < 8; ++w)
            s += reinterpret_cast<const float*>(&sKred[w][l])[comp];
        g_K[bt * DD + tid] = s;
    }
}

// ---------------------------------------------------------------------------
// Kernel 2 (FUSED m+scores): per (b, 8-q tile) — 256 CTAs, warp = 1 q row.
// ---------------------------------------------------------------------------
__global__ void __launch_bounds__(256)
mscores_kernel(const float* __restrict__ wt2) {
    const int b = blockIdx.x, qt = blockIdx.y;
    const int tid = threadIdx.x;
    const int warp = tid >> 5, lane = tid & 31;

    __shared__ float sQ[8 * NN];
    __shared__ float sM[8 * DD];
    __shared__ float sK[TT * 129];

    for (int i = tid; i < 8 * NN; i += 256)
        sQ[i] = g_Q[(b * TT + qt * 8) * NN + i];
    for (int i = tid; i < TT * DD; i += 256) {
        const int k = i >> 7, d = i & 127;
        sK[k * 129 + d] = g_K[(b * TT + k) * DD + d];
    }
    __syncthreads();

    {
        const int q = warp;
        const float* qrow = sQ + q * NN;
        float acc[4] = {0.f, 0.f, 0.f, 0.f};
        const float* w2p = wt2 + lane;
        #pragma unroll 4
        for (int n = 0; n < NN; ++n) {
            const float qv = qrow[n];
            #pragma unroll
            for (int j = 0; j < 4; ++j)
                acc[j] += qv * w2p[n * DD + 32 * j];
        }
        #pragma unroll
        for (int j = 0; j < 4; ++j)
            sM[q * DD + lane + 32 * j] = acc[j];
    }
    __syncthreads();

    #pragma unroll
    for (int pi = 0; pi < 2; ++pi) {
        const int p = pi * 256 + tid;
        const int q = p >> 6, k = p & 63;
        float acc = 0.f;
        #pragma unroll 8
        for (int d = 0; d < DD; ++d)
            acc += sM[q * DD + d] * sK[k * 129 + d];
        g_S[(b * TT + qt * 8 + q) * TT + k] = acc;
    }
}

// ---------------------------------------------------------------------------
// Kernel 3: softmax over BATCH axis + transpose + bf16 hi/lo pre-pack,
// written PRE-PADDED (stride 36) so mix can bulk-copy A contiguously.
// ---------------------------------------------------------------------------
__global__ void __launch_bounds__(256)
softmax_kernel() {
    const int warp = threadIdx.x >> 5, lane = threadIdx.x & 31;
    const int w  = blockIdx.x * 8 + warp;
    const int a  = w >> 5, tp = w & 31;

    const float x0 = g_S[lane * (TT * TT) + (2 * tp) * TT + a];
    const float x1 = g_S[lane * (TT * TT) + (2 * tp + 1) * TT + a];
    float m0 = x0, m1 = x1;
    #pragma unroll
    for (int off = 16; off > 0; off >>= 1) {
        m0 = fmaxf(m0, __shfl_xor_sync(0xffffffffu, m0, off));
        m1 = fmaxf(m1, __shfl_xor_sync(0xffffffffu, m1, off));
    }
    const float e0 = __expf(x0 - m0), e1 = __expf(x1 - m1);
    float s0 = e0, s1 = e1;
    #pragma unroll
    for (int off = 16; off > 0; off >>= 1) {
        s0 += __shfl_xor_sync(0xffffffffu, s0, off);
        s1 += __shfl_xor_sync(0xffffffffu, s1, off);
    }
    const float v0 = e0 / s0, v1 = e1 / s1;
    const float h0 = bf16_round(v0), h1 = bf16_round(v1);
    const int idx = a * SA_STRIDE + tp;
    g_Ah[lane * A_WORDS + idx] = pack_bf16x2(h0, h1);
    g_Al[lane * A_WORDS + idx] = pack_bf16x2(v0 - h0, v1 - h1);
}

// ---------------------------------------------------------------------------
// Kernel 4 (TENSOR) — round-13 proven best (mix 128.0us):
// mixed[a,c] = sum_t att^T[a,t]*src[t,c]; out = mixed + src.
// bf16-split MMA; 64x256 tile; 2 CTAs/SM; bulk-engine loads (mbarrier) and
// staged bulk stores; fused epilogue (RMW is thread-local -> no extra sync).
// ---------------------------------------------------------------------------
#define SS_STRIDE 260   // floats; row pitch 1040 B (16B-aligned); conflict-free
// bytes: sS 66560 + sAh 9216 + sAl 9216 + mbar 16 = 85008
#define MIX_SMEM_BYTES 85008
#define TOTAL_TX (TT*1024 + 2*A_BYTES)   // 65536 + 18432 = 83968

__device__ __forceinline__ void mma_bf16(float c[4],
                                         uint32_t a0, uint32_t a1,
                                         uint32_t a2, uint32_t a3,
                                         uint32_t b0, uint32_t b1) {
    asm volatile(
        "mma.sync.aligned.m16n8k16.row.col.f32.bf16.bf16.f32 "
        "{%0,%1,%2,%3}, {%4,%5,%6,%7}, {%8,%9}, {%0,%1,%2,%3};"
        : "+f"(c[0]), "+f"(c[1]), "+f"(c[2]), "+f"(c[3])
        : "r"(a0), "r"(a1), "r"(a2), "r"(a3), "r"(b0), "r"(b1));
}

__global__ void __launch_bounds__(256, 2)
mix_kernel(const float* __restrict__ src, float* __restrict__ out) {
    extern __shared__ float smem[];
    float*    sS  = smem;                               // [64][260]
    uint32_t* sAh = (uint32_t*)(smem + TT * SS_STRIDE); // [64][36] padded
    uint32_t* sAl = sAh + A_WORDS;
    uint64_t* mb  = (uint64_t*)(sAl + A_WORDS);

    const int b    = blockIdx.y;
    const int tid  = threadIdx.x;
    const int warp = tid >> 5, lane = tid & 31;
    const int colbase = blockIdx.x * 256;

    const uint32_t sS_a  = (uint32_t)__cvta_generic_to_shared(sS);
    const uint32_t sAh_a = (uint32_t)__cvta_generic_to_shared(sAh);
    const uint32_t sAl_a = (uint32_t)__cvta_generic_to_shared(sAl);
    const uint32_t mb_a  = (uint32_t)__cvta_generic_to_shared(mb);

    const float* sb = src + (size_t)b * TT * ND + colbase;

    // --- mbarrier setup + bulk loads (64 rows x 1KB + 2 A arrays) ---
    if (tid == 0) mbar_init(mb_a, 1);
    __syncthreads();
    if (tid == 0) mbar_expect_tx(mb_a, TOTAL_TX);
    __syncthreads();
    if (tid < TT) {
        bulk_ld(sS_a + tid * (SS_STRIDE * 4), sb + (size_t)tid * ND, 1024, mb_a);
    } else if (tid == 64) {
        bulk_ld(sAh_a, g_Ah + b * A_WORDS, A_BYTES, mb_a);
    } else if (tid == 65) {
        bulk_ld(sAl_a, g_Al + b * A_WORDS, A_BYTES, mb_a);
    }
    mbar_wait(mb_a, 0);

    const int g   = lane >> 2;
    const int tg  = lane & 3;
    const int n0w = warp * 32;

    float acc[4][4][4];
    #pragma unroll
    for (int mt = 0; mt < 4; ++mt)
        #pragma unroll
        for (int nt = 0; nt < 4; ++nt)
            #pragma unroll
            for (int f = 0; f < 4; ++f) acc[mt][nt][f] = 0.f;

    #pragma unroll
    for (int ks = 0; ks < 4; ++ks) {
        // --- stage B fragments for all 4 nt (16 regs) ---
        uint32_t Bh0[4], Bh1[4], Bl0[4], Bl1[4];
        #pragma unroll
        for (int nt = 0; nt < 4; ++nt) {
            const int c  = n0w + nt * 8 + g;
            const int t0 = ks * 16 + 2 * tg;
            const float v0 = sS[(t0)     * SS_STRIDE + c];
            const float v1 = sS[(t0 + 1) * SS_STRIDE + c];
            const float v2 = sS[(t0 + 8) * SS_STRIDE + c];
            const float v3 = sS[(t0 + 9) * SS_STRIDE + c];
            const float h0 = bf16_round(v0), h1 = bf16_round(v1);
            const float h2 = bf16_round(v2), h3 = bf16_round(v3);
            Bh0[nt] = pack_bf16x2(h0, h1);
            Bh1[nt] = pack_bf16x2(h2, h3);
            Bl0[nt] = pack_bf16x2(v0 - h0, v1 - h1);
            Bl1[nt] = pack_bf16x2(v2 - h2, v3 - h3);
        }
        // --- per-mt: load A just-in-time (8 regs), fire 12 MMAs ---
        #pragma unroll
        for (int mt = 0; mt < 4; ++mt) {
            const int r0 = (mt * 16 + g) * SA_STRIDE + ks * 8 + tg;
            const int r1 = r0 + 8 * SA_STRIDE;
            const uint32_t ah0 = sAh[r0],     ah1 = sAh[r1];
            const uint32_t ah2 = sAh[r0 + 4], ah3 = sAh[r1 + 4];
            const uint32_t al0 = sAl[r0],     al1 = sAl[r1];
            const uint32_t al2 = sAl[r0 + 4], al3 = sAl[r1 + 4];
            #pragma unroll
            for (int nt = 0; nt < 4; ++nt) {
                mma_bf16(acc[mt][nt], ah0, ah1, ah2, ah3, Bh0[nt], Bh1[nt]);
                mma_bf16(acc[mt][nt], al0, al1, al2, al3, Bh0[nt], Bh1[nt]);
                mma_bf16(acc[mt][nt], ah0, ah1, ah2, ah3, Bl0[nt], Bl1[nt]);
            }
        }
    }

    // --- fused epilogue: residual add + store-stage (thread-local RMW on sS,
    //     each element read and written by exactly one thread) ---
    __syncthreads();   // all B-fragment LDS reads of sS complete before overwrite
    #pragma unroll
    for (int mt = 0; mt < 4; ++mt) {
        const int a0 = mt * 16 + g;
        #pragma unroll
        for (int nt = 0; nt < 4; ++nt) {
            const int c = n0w + nt * 8 + 2 * tg;
            float2* p0 = reinterpret_cast<float2*>(sS + a0 * SS_STRIDE + c);
            float2* p1 = reinterpret_cast<float2*>(sS + (a0 + 8) * SS_STRIDE + c);
            const float2 r0 = *p0;
            const float2 r1 = *p1;
            *p0 = make_float2(acc[mt][nt][0] + r0.x, acc[mt][nt][1] + r0.y);
            *p1 = make_float2(acc[mt][nt][2] + r1.x, acc[mt][nt][3] + r1.y);
        }
    }
    __syncthreads();

    float* ob = out + (size_t)b * TT * ND + colbase;
    if (tid < TT) {
        asm volatile("fence.proxy.async;" ::: "memory");
        bulk_st(ob + (size_t)tid * ND, sS_a + tid * (SS_STRIDE * 4), 1024);
        asm volatile("cp.async.bulk.commit_group;" ::: "memory");
        asm volatile("cp.async.bulk.wait_group.read 0;" ::: "memory");
    }
}

// ---------------------------------------------------------------------------
extern "C" void kernel_launch(void* const* d_in, const int* in_sizes, int n_in,
                              void* d_out, int out_size) {
    const float *src = nullptr, *wt1 = nullptr, *wt2 = nullptr, *wt3 = nullptr;
    for (int i = 0; i < n_in; ++i) {
        const int s = in_sizes[i];
        if      (s == BB * TT * NN * DD) src = (const float*)d_in[i];
        else if (s == DD)                wt1 = (const float*)d_in[i];
        else if (s == NN * DD)           wt2 = (const float*)d_in[i];
        else if (s == NN)                wt3 = (const float*)d_in[i];
    }
    float* out = (float*)d_out;

    static bool attr_done = false;
    if (!attr_done) {
        cudaFuncSetAttribute(mix_kernel,
                             cudaFuncAttributeMaxDynamicSharedMemorySize,
                             MIX_SMEM_BYTES);
        attr_done = true;
    }

    qk_kernel<<<BT, 256>>>(src, wt1, wt3);
    mscores_kernel<<<dim3(BB, 8), 256>>>(wt2);
    softmax_kernel<<<256, 256>>>();
    mix_kernel<<<dim3(ND / 256, BB), 256, MIX_SMEM_BYTES>>>(src, out);
}

// round 17
// speedup vs baseline: 1.1414x; 1.0518x over previous
#include <cuda_runtime.h>
#include <cuda_bf16.h>
#include <cstring>
#include <cstdint>

// Shapes
#define BB 32
#define TT 64
#define NN 300
#define DD 128
#define ND (NN*DD)          // 38400
#define BT (BB*TT)          // 2048

#define SA_STRIDE 36        // A row stride (uint32), padded, conflict-free
#define A_WORDS (TT*SA_STRIDE)   // 2304 u32 = 9216 B per batch per array
#define A_BYTES 9216

// Scratch (static __device__ — no allocation allowed)
__device__ float    g_Q[BB*TT*NN];      // [b,t,n]
__device__ float    g_K[BB*TT*DD];      // [b,t,d]
__device__ float    g_S[BB*TT*TT];      // scores [b,q,k]
__device__ uint32_t g_Ah[BB*A_WORDS];   // att^T bf16x2 hi, PRE-PADDED stride 36
__device__ uint32_t g_Al[BB*A_WORDS];   // att^T bf16x2 lo, PRE-PADDED stride 36

__device__ __forceinline__ float bf16_round(float v) {
    return __bfloat162float(__float2bfloat16_rn(v));
}
// pack two floats as bf16x2; 'lo' goes to bits [15:0] (lower k index)
__device__ __forceinline__ uint32_t pack_bf16x2(float lo, float hi) {
    uint32_t r;
    asm("cvt.rn.bf16x2.f32 %0, %1, %2;" : "=r"(r) : "f"(hi), "f"(lo));
    return r;
}

// ---- bulk-copy / mbarrier primitives ----
__device__ __forceinline__ void bulk_ld(uint32_t dst_smem, const void* src,
                                        uint32_t bytes, uint32_t mbar) {
    asm volatile(
        "cp.async.bulk.shared::cluster.global.mbarrier::complete_tx::bytes "
        "[%0], [%1], %2, [%3];"
        :: "r"(dst_smem), "l"(src), "r"(bytes), "r"(mbar) : "memory");
}
__device__ __forceinline__ void bulk_st(void* dst, uint32_t src_smem, uint32_t bytes) {
    asm volatile(
        "cp.async.bulk.global.shared::cta.bulk_group [%0], [%1], %2;"
        :: "l"(dst), "r"(src_smem), "r"(bytes) : "memory");
}
__device__ __forceinline__ void mbar_init(uint32_t mbar, uint32_t count) {
    asm volatile("mbarrier.init.shared.b64 [%0], %1;" :: "r"(mbar), "r"(count) : "memory");
}
__device__ __forceinline__ void mbar_expect_tx(uint32_t mbar, uint32_t bytes) {
    asm volatile("mbarrier.arrive.expect_tx.shared.b64 _, [%0], %1;"
                 :: "r"(mbar), "r"(bytes) : "memory");
}
__device__ __forceinline__ void mbar_wait(uint32_t mbar, uint32_t parity) {
    uint32_t done = 0;
    while (!done) {
        asm volatile(
            "{\n\t.reg .pred p;\n\t"
            "mbarrier.try_wait.parity.shared::cta.b64 p, [%1], %2;\n\t"
            "selp.b32 %0, 1, 0, p;\n\t}"
            : "=r"(done) : "r"(mbar), "r"(parity) : "memory");
    }
}

// ---------------------------------------------------------------------------
// Kernel 1 (FUSED, single pass over src):
//   Q[bt,n] = dot(src[bt,n,:], wt1);  K[bt,d] = sum_n wt3[n]*src[bt,n,d]
// ---------------------------------------------------------------------------
#define SP_STRIDE 33

__global__ void __launch_bounds__(256)
qk_kernel(const float* __restrict__ src,
          const float* __restrict__ wt1,
          const float* __restrict__ wt3) {
    const int bt  = blockIdx.x;
    const int tid = threadIdx.x;
    const float* base = src + (size_t)bt * ND;

    __shared__ float  sw3[NN];
    __shared__ float  sP[NN * SP_STRIDE];
    __shared__ float4 sKred[8][32];

    for (int i = tid; i < NN; i += 256) sw3[i] = wt3[i];
    __syncthreads();

    const int warp = tid >> 5, lane = tid & 31;
    const float4 w1v = reinterpret_cast<const float4*>(wt1)[lane];
    float4 kacc = make_float4(0.f, 0.f, 0.f, 0.f);

    #pragma unroll 8
    for (int n = warp; n < NN; n += 8) {
        const float4 v = reinterpret_cast<const float4*>(base + n * DD)[lane];
        const float w3n = sw3[n];
        kacc.x += w3n * v.x; kacc.y += w3n * v.y;
        kacc.z += w3n * v.z; kacc.w += w3n * v.w;
        sP[n * SP_STRIDE + lane] =
            v.x * w1v.x + v.y * w1v.y + v.z * w1v.z + v.w * w1v.w;
    }

    sKred[warp][lane] = kacc;
    __syncthreads();

    for (int n = tid; n < NN; n += 256) {
        const float* row = sP + n * SP_STRIDE;
        float s = 0.f;
        #pragma unroll
        for (int j = 0; j < 32; ++j) s += row[j];
        g_Q[bt * NN + n] = s;
    }

    if (tid < 128) {
        const int l = tid >> 2, comp = tid & 3;
        float s = 0.f;
        #pragma unroll
        for (int w = 0; w < 8; ++w)
            s += reinterpret_cast<const float*>(&sKred[w][l])[comp];
        g_K[bt * DD + tid] = s;
    }
}

// ---------------------------------------------------------------------------
// Kernel 2 (FUSED m+scores): per (b, 8-q tile) — 256 CTAs, warp = 1 q row.
// ---------------------------------------------------------------------------
__global__ void __launch_bounds__(256)
mscores_kernel(const float* __restrict__ wt2) {
    const int b = blockIdx.x, qt = blockIdx.y;
    const int tid = threadIdx.x;
    const int warp = tid >> 5, lane = tid & 31;

    __shared__ float sQ[8 * NN];
    __shared__ float sM[8 * DD];
    __shared__ float sK[TT * 129];

    for (int i = tid; i < 8 * NN; i += 256)
        sQ[i] = g_Q[(b * TT + qt * 8) * NN + i];
    for (int i = tid; i < TT * DD; i += 256) {
        const int k = i >> 7, d = i & 127;
        sK[k * 129 + d] = g_K[(b * TT + k) * DD + d];
    }
    __syncthreads();

    {
        const int q = warp;
        float acc[4] = {0.f, 0.f, 0.f, 0.f};
        #pragma unroll 4
        for (int n = 0; n < NN; ++n) {
            const float qv = sQ[q * NN + n];
            const float* w2 = wt2 + n * DD;
            #pragma unroll
            for (int j = 0; j < 4; ++j)
                acc[j] += qv * w2[lane + 32 * j];
        }
        #pragma unroll
        for (int j = 0; j < 4; ++j)
            sM[q * DD + lane + 32 * j] = acc[j];
    }
    __syncthreads();

    #pragma unroll
    for (int pi = 0; pi < 2; ++pi) {
        const int p = pi * 256 + tid;
        const int q = p >> 6, k = p & 63;
        float acc = 0.f;
        #pragma unroll 8
        for (int d = 0; d < DD; ++d)
            acc += sM[q * DD + d] * sK[k * 129 + d];
        g_S[(b * TT + qt * 8 + q) * TT + k] = acc;
    }
}

// ---------------------------------------------------------------------------
// Kernel 3: softmax over BATCH axis + transpose + bf16 hi/lo pre-pack,
// written PRE-PADDED (stride 36) so mix can bulk-copy A contiguously.
// ---------------------------------------------------------------------------
__global__ void __launch_bounds__(256)
softmax_kernel() {
    const int warp = threadIdx.x >> 5, lane = threadIdx.x & 31;
    const int w  = blockIdx.x * 8 + warp;
    const int a  = w >> 5, tp = w & 31;

    const float x0 = g_S[lane * (TT * TT) + (2 * tp) * TT + a];
    const float x1 = g_S[lane * (TT * TT) + (2 * tp + 1) * TT + a];
    float m0 = x0, m1 = x1;
    #pragma unroll
    for (int off = 16; off > 0; off >>= 1) {
        m0 = fmaxf(m0, __shfl_xor_sync(0xffffffffu, m0, off));
        m1 = fmaxf(m1, __shfl_xor_sync(0xffffffffu, m1, off));
    }
    const float e0 = __expf(x0 - m0), e1 = __expf(x1 - m1);
    float s0 = e0, s1 = e1;
    #pragma unroll
    for (int off = 16; off > 0; off >>= 1) {
        s0 += __shfl_xor_sync(0xffffffffu, s0, off);
        s1 += __shfl_xor_sync(0xffffffffu, s1, off);
    }
    const float v0 = e0 / s0, v1 = e1 / s1;
    const float h0 = bf16_round(v0), h1 = bf16_round(v1);
    const int idx = a * SA_STRIDE + tp;
    g_Ah[lane * A_WORDS + idx] = pack_bf16x2(h0, h1);
    g_Al[lane * A_WORDS + idx] = pack_bf16x2(v0 - h0, v1 - h1);
}

// ---------------------------------------------------------------------------
// Kernel 4 (TENSOR) — round-13 proven best (mix 128.0us, total 244.2us):
// mixed[a,c] = sum_t att^T[a,t]*src[t,c]; out = mixed + src.
// bf16-split MMA; 64x256 tile; 2 CTAs/SM; bulk-engine loads (mbarrier) and
// staged bulk stores. Epilogue: residual reads BEFORE sync (overlaps mainloop
// drain), then write-stage, then bulk store.
// ---------------------------------------------------------------------------
#define SS_STRIDE 260   // floats; row pitch 1040 B (16B-aligned); conflict-free
// bytes: sS 66560 + sAh 9216 + sAl 9216 + mbar 16 = 85008
#define MIX_SMEM_BYTES 85008
#define TOTAL_TX (TT*1024 + 2*A_BYTES)   // 65536 + 18432 = 83968

__device__ __forceinline__ void mma_bf16(float c[4],
                                         uint32_t a0, uint32_t a1,
                                         uint32_t a2, uint32_t a3,
                                         uint32_t b0, uint32_t b1) {
    asm volatile(
        "mma.sync.aligned.m16n8k16.row.col.f32.bf16.bf16.f32 "
        "{%0,%1,%2,%3}, {%4,%5,%6,%7}, {%8,%9}, {%0,%1,%2,%3};"
        : "+f"(c[0]), "+f"(c[1]), "+f"(c[2]), "+f"(c[3])
        : "r"(a0), "r"(a1), "r"(a2), "r"(a3), "r"(b0), "r"(b1));
}

__global__ void __launch_bounds__(256, 2)
mix_kernel(const float* __restrict__ src, float* __restrict__ out) {
    extern __shared__ float smem[];
    float*    sS  = smem;                               // [64][260]
    uint32_t* sAh = (uint32_t*)(smem + TT * SS_STRIDE); // [64][36] padded
    uint32_t* sAl = sAh + A_WORDS;
    uint64_t* mb  = (uint64_t*)(sAl + A_WORDS);

    const int b    = blockIdx.y;
    const int tid  = threadIdx.x;
    const int warp = tid >> 5, lane = tid & 31;
    const int colbase = blockIdx.x * 256;

    const uint32_t sS_a  = (uint32_t)__cvta_generic_to_shared(sS);
    const uint32_t sAh_a = (uint32_t)__cvta_generic_to_shared(sAh);
    const uint32_t sAl_a = (uint32_t)__cvta_generic_to_shared(sAl);
    const uint32_t mb_a  = (uint32_t)__cvta_generic_to_shared(mb);

    const float* sb = src + (size_t)b * TT * ND + colbase;

    // --- mbarrier setup + bulk loads (64 rows x 1KB + 2 A arrays) ---
    if (tid == 0) mbar_init(mb_a, 1);
    __syncthreads();
    if (tid == 0) mbar_expect_tx(mb_a, TOTAL_TX);
    __syncthreads();
    if (tid < TT) {
        bulk_ld(sS_a + tid * (SS_STRIDE * 4), sb + (size_t)tid * ND, 1024, mb_a);
    } else if (tid == 64) {
        bulk_ld(sAh_a, g_Ah + b * A_WORDS, A_BYTES, mb_a);
    } else if (tid == 65) {
        bulk_ld(sAl_a, g_Al + b * A_WORDS, A_BYTES, mb_a);
    }
    mbar_wait(mb_a, 0);

    const int g   = lane >> 2;
    const int tg  = lane & 3;
    const int n0w = warp * 32;

    float acc[4][4][4];
    #pragma unroll
    for (int mt = 0; mt < 4; ++mt)
        #pragma unroll
        for (int nt = 0; nt < 4; ++nt)
            #pragma unroll
            for (int f = 0; f < 4; ++f) acc[mt][nt][f] = 0.f;

    #pragma unroll
    for (int ks = 0; ks < 4; ++ks) {
        // --- stage B fragments for all 4 nt (16 regs) ---
        uint32_t Bh0[4], Bh1[4], Bl0[4], Bl1[4];
        #pragma unroll
        for (int nt = 0; nt < 4; ++nt) {
            const int c  = n0w + nt * 8 + g;
            const int t0 = ks * 16 + 2 * tg;
            const float v0 = sS[(t0)     * SS_STRIDE + c];
            const float v1 = sS[(t0 + 1) * SS_STRIDE + c];
            const float v2 = sS[(t0 + 8) * SS_STRIDE + c];
            const float v3 = sS[(t0 + 9) * SS_STRIDE + c];
            const float h0 = bf16_round(v0), h1 = bf16_round(v1);
            const float h2 = bf16_round(v2), h3 = bf16_round(v3);
            Bh0[nt] = pack_bf16x2(h0, h1);
            Bh1[nt] = pack_bf16x2(h2, h3);
            Bl0[nt] = pack_bf16x2(v0 - h0, v1 - h1);
            Bl1[nt] = pack_bf16x2(v2 - h2, v3 - h3);
        }
        // --- per-mt: load A just-in-time (8 regs), fire 12 MMAs ---
        #pragma unroll
        for (int mt = 0; mt < 4; ++mt) {
            const int r0 = (mt * 16 + g) * SA_STRIDE + ks * 8 + tg;
            const int r1 = r0 + 8 * SA_STRIDE;
            const uint32_t ah0 = sAh[r0],     ah1 = sAh[r1];
            const uint32_t ah2 = sAh[r0 + 4], ah3 = sAh[r1 + 4];
            const uint32_t al0 = sAl[r0],     al1 = sAl[r1];
            const uint32_t al2 = sAl[r0 + 4], al3 = sAl[r1 + 4];
            #pragma unroll
            for (int nt = 0; nt < 4; ++nt) {
                mma_bf16(acc[mt][nt], ah0, ah1, ah2, ah3, Bh0[nt], Bh1[nt]);
                mma_bf16(acc[mt][nt], al0, al1, al2, al3, Bh0[nt], Bh1[nt]);
                mma_bf16(acc[mt][nt], ah0, ah1, ah2, ah3, Bl0[nt], Bl1[nt]);
            }
        }
    }

    // --- epilogue: add fp32 residual from sS (reads BEFORE sync, overlapping
    //     mainloop drain), then stage into sS + bulk store ---
    #pragma unroll
    for (int mt = 0; mt < 4; ++mt) {
        const int a0 = mt * 16 + g;
        #pragma unroll
        for (int nt = 0; nt < 4; ++nt) {
            const int c = n0w + nt * 8 + 2 * tg;
            const float2 r0 = *reinterpret_cast<const float2*>(sS + a0 * SS_STRIDE + c);
            const float2 r1 = *reinterpret_cast<const float2*>(sS + (a0 + 8) * SS_STRIDE + c);
            acc[mt][nt][0] += r0.x; acc[mt][nt][1] += r0.y;
            acc[mt][nt][2] += r1.x; acc[mt][nt][3] += r1.y;
        }
    }
    __syncthreads();
    #pragma unroll
    for (int mt = 0; mt < 4; ++mt) {
        const int a0 = mt * 16 + g;
        #pragma unroll
        for (int nt = 0; nt < 4; ++nt) {
            const int c = n0w + nt * 8 + 2 * tg;
            *reinterpret_cast<float2*>(sS + a0 * SS_STRIDE + c) =
                make_float2(acc[mt][nt][0], acc[mt][nt][1]);
            *reinterpret_cast<float2*>(sS + (a0 + 8) * SS_STRIDE + c) =
                make_float2(acc[mt][nt][2], acc[mt][nt][3]);
        }
    }
    __syncthreads();

    float* ob = out + (size_t)b * TT * ND + colbase;
    if (tid < TT) {
        asm volatile("fence.proxy.async;" ::: "memory");
        bulk_st(ob + (size_t)tid * ND, sS_a + tid * (SS_STRIDE * 4), 1024);
        asm volatile("cp.async.bulk.commit_group;" ::: "memory");
        asm volatile("cp.async.bulk.wait_group.read 0;" ::: "memory");
    }
}

// ---------------------------------------------------------------------------
extern "C" void kernel_launch(void* const* d_in, const int* in_sizes, int n_in,
                              void* d_out, int out_size) {
    const float *src = nullptr, *wt1 = nullptr, *wt2 = nullptr, *wt3 = nullptr;
    for (int i = 0; i < n_in; ++i) {
        const int s = in_sizes[i];
        if      (s == BB * TT * NN * DD) src = (const float*)d_in[i];
        else if (s == DD)                wt1 = (const float*)d_in[i];
        else if (s == NN * DD)           wt2 = (const float*)d_in[i];
        else if (s == NN)                wt3 = (const float*)d_in[i];
    }
    float* out = (float*)d_out;

    static bool attr_done = false;
    if (!attr_done) {
        cudaFuncSetAttribute(mix_kernel,
                             cudaFuncAttributeMaxDynamicSharedMemorySize,
                             MIX_SMEM_BYTES);
        attr_done = true;
    }

    qk_kernel<<<BT, 256>>>(src, wt1, wt3);
    mscores_kernel<<<dim3(BB, 8), 256>>>(wt2);
    softmax_kernel<<<256, 256>>>();
    mix_kernel<<<dim3(ND / 256, BB), 256, MIX_SMEM_BYTES>>>(src, out);
}